// round 16
// baseline (speedup 1.0000x reference)
#include <cuda_runtime.h>
#include <cuda_bf16.h>
#include <cstdint>

#define Pn 64
#define Sn 4096
#define Dn 128
#define TM 32            // sample rows per block
#define NTHR 256         // precompute kernel threads
#define MTHR 512         // main kernel threads
#define XSTR 136         // bf16 operand-tile k-stride (128 + 8 pad) -> conflict-free frags
#define SSTR 132         // fp32 score-tile stride

// ---------------- persistent device scratch (no allocs allowed) ----------------
__device__ __align__(16) uint16_t imgA_hi[Dn * XSTR], imgA_lo[Dn * XSTR];  // stage1 B-op
__device__ __align__(16) uint16_t imgB_hi[Dn * XSTR], imgB_lo[Dn * XSTR];  // stage2 B-op
__device__ __align__(16) uint16_t imgW_hi[Dn * XSTR], imgW_lo[Dn * XSTR];  // stage3 B-op
__device__ __align__(16) float gc[Dn];   // folded bq * K^T / 8 (stage-1 bias)

// ---------------- helpers ----------------
#define CP_COMMIT()  asm volatile("cp.async.commit_group;" ::: "memory")
#define CP_WAIT(n)   asm volatile("cp.async.wait_group %0;" :: "n"(n) : "memory")

__device__ __forceinline__ void cvt_split2(float a0, float a1, uint32_t& hi, uint32_t& lo) {
    asm("cvt.rn.bf16x2.f32 %0, %1, %2;" : "=r"(hi) : "f"(a1), "f"(a0));
    float f0 = __uint_as_float(hi << 16);
    float f1 = __uint_as_float(hi & 0xFFFF0000u);
    asm("cvt.rn.bf16x2.f32 %0, %1, %2;" : "=r"(lo) : "f"(a1 - f1), "f"(a0 - f0));
}
__device__ __forceinline__ void cvt_split4(float a0, float a1, float a2, float a3,
                                           unsigned long long& hi, unsigned long long& lo) {
    uint32_t u0, u1, v0, v1;
    cvt_split2(a0, a1, u0, v0);
    cvt_split2(a2, a3, u1, v1);
    asm("mov.b64 %0, {%1, %2};" : "=l"(hi) : "r"(u0), "r"(u1));
    asm("mov.b64 %0, {%1, %2};" : "=l"(lo) : "r"(v0), "r"(v1));
}
__device__ __forceinline__ uint32_t smem_to_u32(const void* p) {
    uint32_t a;
    asm("{ .reg .u64 t; cvta.to.shared.u64 t, %1; cvt.u32.u64 %0, t; }" : "=r"(a) : "l"(p));
    return a;
}

// ============================================================
// Single precompute kernel (unchanged from passing R15).
// ============================================================
__global__ __launch_bounds__(NTHR) void pre_all_kernel(
    const float* __restrict__ proxies,
    const float* __restrict__ Wq, const float* __restrict__ bq,
    const float* __restrict__ Wk, const float* __restrict__ bk,
    const float* __restrict__ Wv, const float* __restrict__ bv,
    const float* __restrict__ Wo, const float* __restrict__ Wfc)
{
    __shared__ __align__(16) float prS[Dn];
    __shared__ __align__(16) float kh[64];
    __shared__ __align__(16) float vh[64];

    const int col = blockIdx.x;
    const int h = col >> 6, p = col & 63;
    const int t = threadIdx.x;
    const int w = t >> 5, l = t & 31;

    if (t < 32)
        *reinterpret_cast<float4*>(prS + t * 4) =
            reinterpret_cast<const float4*>(proxies + p * Dn)[t];
    __syncthreads();

    {   // warp-cooperative dots: warps 0-3 -> kh, warps 4-7 -> vh
        const float* Wsrc = (w < 4) ? Wk : Wv;
        const float* bsrc = (w < 4) ? bk : bv;
        float* dst = (w < 4) ? kh : vh;
        const int j0 = (w & 3) * 16;
        float4 pv = *reinterpret_cast<const float4*>(prS + l * 4);
#pragma unroll
        for (int jj = 0; jj < 16; jj++) {
            int j = j0 + jj;
            float4 w4 = *reinterpret_cast<const float4*>(Wsrc + (h * 64 + j) * Dn + l * 4);
            float s = w4.x * pv.x + w4.y * pv.y + w4.z * pv.z + w4.w * pv.w;
#pragma unroll
            for (int o = 16; o; o >>= 1) s += __shfl_xor_sync(0xffffffffu, s, o);
            if (l == 0) dst[j] = s + bsrc[h * 64 + j];
        }
    }
    __syncthreads();

    if (w == 0) {   // gc[col]
        float s = bq[h * 64 + l] * kh[l] + bq[h * 64 + 32 + l] * kh[32 + l];
#pragma unroll
        for (int o = 16; o; o >>= 1) s += __shfl_xor_sync(0xffffffffu, s, o);
        if (l == 0) gc[col] = s * 0.125f;
    }

    if (t < Dn) {
        float a = 0.f;
#pragma unroll 16
        for (int j = 0; j < 64; j++) a += Wq[(h * 64 + j) * Dn + t] * kh[j];
        a *= 0.125f;
        {
            __nv_bfloat16 hb = __float2bfloat16(a);
            float fh = __bfloat162float(hb);
            __nv_bfloat16 lb = __float2bfloat16(a - fh);
            imgA_hi[col * XSTR + t] = __bfloat16_as_ushort(hb);
            imgA_lo[col * XSTR + t] = __bfloat16_as_ushort(lb);
        }
        float wv = Wfc[col * Dn + t];
        {
            __nv_bfloat16 hb = __float2bfloat16(wv);
            float fh = __bfloat162float(hb);
            __nv_bfloat16 lb = __float2bfloat16(wv - fh);
            imgW_hi[col * XSTR + t] = __bfloat16_as_ushort(hb);
            imgW_lo[col * XSTR + t] = __bfloat16_as_ushort(lb);
        }
        if (t < 8) {   // zero k-pad (determinism)
            imgA_hi[col * XSTR + Dn + t] = 0; imgA_lo[col * XSTR + Dn + t] = 0;
            imgB_hi[col * XSTR + Dn + t] = 0; imgB_lo[col * XSTR + Dn + t] = 0;
            imgW_hi[col * XSTR + Dn + t] = 0; imgW_lo[col * XSTR + Dn + t] = 0;
        }
    } else {
        const int j2 = t - Dn;
        const float4* wo = reinterpret_cast<const float4*>(Wo + j2 * Dn + h * 64);
        float s = 0.f;
#pragma unroll
        for (int q = 0; q < 16; q++) {
            float4 w4 = wo[q];
            float4 v4 = *reinterpret_cast<const float4*>(vh + q * 4);
            s += w4.x * v4.x + w4.y * v4.y + w4.z * v4.z + w4.w * v4.w;
        }
        __nv_bfloat16 hb = __float2bfloat16(s);
        float fh = __bfloat162float(hb);
        __nv_bfloat16 lb = __float2bfloat16(s - fh);
        imgB_hi[j2 * XSTR + col] = __bfloat16_as_ushort(hb);
        imgB_lo[j2 * XSTR + col] = __bfloat16_as_ushort(lb);
    }
}

// ============================================================
// Main kernel smem layout (bytes) — single B slot -> 2 blocks/SM
// ============================================================
#define SM_GC   0
#define SM_BO   512
#define SM_BFC  1024
#define SM_AHI  1536
#define SM_ALO  (SM_AHI + TM * XSTR * 2)     // 10240
#define SM_SC   (SM_ALO + TM * XSTR * 2)     // 18944
#define SM_BH   (SM_SC + TM * SSTR * 4)      // 35840
#define SM_BL   (SM_BH + Dn * XSTR * 2)      // 70656
#define SM_TOT  (SM_BL + Dn * XSTR * 2)      // 105472 B

__device__ __forceinline__ void cpa_img(uint32_t sdst, const uint16_t* src, int tid) {
    // 128*XSTR bf16 = 34816 B = 2176 x 16B chunks, 512 threads
#pragma unroll
    for (int i = 0; i < 5; i++) {
        int idx = tid + i * MTHR;
        if (idx < 2176)
            asm volatile("cp.async.cg.shared.global [%0], [%1], 16;"
                         :: "r"(sdst + idx * 16), "l"((const char*)src + idx * 16));
    }
}
__device__ __forceinline__ void cp16(uint32_t d, const void* s) {
    asm volatile("cp.async.ca.shared.global [%0], [%1], 16;" :: "r"(d), "l"(s));
}

// 3-pass split MMA: d += Ahi*Bhi + Ahi*Blo + Alo*Bhi   (warp tile 16x16)
__device__ __forceinline__ void mma_stage(
    const uint16_t* __restrict__ Ah, const uint16_t* __restrict__ Al,
    const uint16_t* __restrict__ Bh, const uint16_t* __restrict__ Bl,
    int m0, int n0, int g, int tg, float d[2][4])
{
#pragma unroll
    for (int nt = 0; nt < 2; nt++)
#pragma unroll
        for (int i = 0; i < 4; i++) d[nt][i] = 0.f;

#pragma unroll
    for (int p = 0; p < 3; p++) {
        const uint16_t* A = (p == 2) ? Al : Ah;
        const uint16_t* B = (p == 1) ? Bl : Bh;
#pragma unroll
        for (int kk = 0; kk < 8; kk++) {
            const uint16_t* ap = A + (m0 + g) * XSTR + kk * 16 + tg * 2;
            uint32_t a0 = *reinterpret_cast<const uint32_t*>(ap);
            uint32_t a1 = *reinterpret_cast<const uint32_t*>(ap + 8 * XSTR);
            uint32_t a2 = *reinterpret_cast<const uint32_t*>(ap + 8);
            uint32_t a3 = *reinterpret_cast<const uint32_t*>(ap + 8 * XSTR + 8);
#pragma unroll
            for (int nt = 0; nt < 2; nt++) {
                const uint16_t* bp = B + (n0 + nt * 8 + g) * XSTR + kk * 16 + tg * 2;
                uint32_t b0 = *reinterpret_cast<const uint32_t*>(bp);
                uint32_t b1 = *reinterpret_cast<const uint32_t*>(bp + 8);
                asm volatile(
                    "mma.sync.aligned.m16n8k16.row.col.f32.bf16.bf16.f32 "
                    "{%0,%1,%2,%3}, {%4,%5,%6,%7}, {%8,%9}, {%0,%1,%2,%3};"
                    : "+f"(d[nt][0]), "+f"(d[nt][1]), "+f"(d[nt][2]), "+f"(d[nt][3])
                    : "r"(a0), "r"(a1), "r"(a2), "r"(a3), "r"(b0), "r"(b1));
            }
        }
    }
}

// ============================================================
// Main fused kernel: grid 128 (TM=32 rows), 512 threads, 2 blocks/SM.
// Warp w (0..15): m0 = (w>>3)*16 rows, n0 = (w&7)*16 cols.
// ============================================================
__global__ __launch_bounds__(MTHR, 2) void gnn_mma_kernel(
    const float* __restrict__ x,
    const float* __restrict__ bo, const float* __restrict__ bfc,
    float* __restrict__ outP, float* __restrict__ outH)
{
    extern __shared__ char smem[];
    const uint32_t su = smem_to_u32(smem);
    uint16_t* Ah = reinterpret_cast<uint16_t*>(smem + SM_AHI);
    uint16_t* Al = reinterpret_cast<uint16_t*>(smem + SM_ALO);
    float*    sc = reinterpret_cast<float*>(smem + SM_SC);
    const uint16_t* Bh = reinterpret_cast<const uint16_t*>(smem + SM_BH);
    const uint16_t* Bl = reinterpret_cast<const uint16_t*>(smem + SM_BL);

    const int tid = threadIdx.x;
    const int w = tid >> 5, lane = tid & 31;
    const int g = lane >> 2, tg = lane & 3;
    const int m0 = (w >> 3) * 16, n0 = (w & 7) * 16;
    const int row0 = blockIdx.x * TM;

    // -------- prologue: biases + B <- imgA ; stage x -> A tiles --------
    cpa_img(su + SM_BH, imgA_hi, tid);
    cpa_img(su + SM_BL, imgA_lo, tid);
    if (tid < 32)      cp16(su + SM_GC  + tid * 16,        (const char*)gc  + tid * 16);
    else if (tid < 64) cp16(su + SM_BO  + (tid - 32) * 16, (const char*)bo  + (tid - 32) * 16);
    else if (tid < 96) cp16(su + SM_BFC + (tid - 64) * 16, (const char*)bfc + (tid - 64) * 16);
    CP_COMMIT();

    {
        const float4* xg = reinterpret_cast<const float4*>(x + (size_t)row0 * Dn);
#pragma unroll
        for (int i = 0; i < 2; i++) {
            int idx = tid + i * MTHR;          // 0..1023 quad of 32x128 tile
            int r = idx >> 5, k0 = (idx & 31) * 4;
            float4 v = xg[idx];
            unsigned long long hi, lo;
            cvt_split4(v.x, v.y, v.z, v.w, hi, lo);
            *reinterpret_cast<unsigned long long*>(Ah + r * XSTR + k0) = hi;
            *reinterpret_cast<unsigned long long*>(Al + r * XSTR + k0) = lo;
        }
    }
    CP_WAIT(0);
    __syncthreads();

    float d[2][4];

    // ==================== stage 1: scores = x @ A + gc ====================
    mma_stage(Ah, Al, Bh, Bl, m0, n0, g, tg, d);
    {
        const float* gcS = reinterpret_cast<const float*>(smem + SM_GC);
#pragma unroll
        for (int nt = 0; nt < 2; nt++) {
            int c = n0 + nt * 8 + tg * 2;
            float2 bv = *reinterpret_cast<const float2*>(gcS + c);
            *reinterpret_cast<float2*>(sc + (m0 + g) * SSTR + c)
                = make_float2(d[nt][0] + bv.x, d[nt][1] + bv.y);
            *reinterpret_cast<float2*>(sc + (m0 + g + 8) * SSTR + c)
                = make_float2(d[nt][2] + bv.x, d[nt][3] + bv.y);
        }
    }
    __syncthreads();          // stage-1 B & A reads complete

    // -------- B <- imgB ; softmax (smem-streamed) -> alpha into A tiles --------
    cpa_img(su + SM_BH, imgB_hi, tid);
    cpa_img(su + SM_BL, imgB_lo, tid);
    CP_COMMIT();
    if (tid < 64) {           // one (row, head) per thread
        const int r = tid >> 1, hh = tid & 1;
        float4* sp4 = reinterpret_cast<float4*>(sc + r * SSTR + hh * 64);
        float mx = -1e30f;
#pragma unroll
        for (int q = 0; q < 16; q++) {
            float4 v = sp4[q];
            mx = fmaxf(mx, fmaxf(fmaxf(v.x, v.y), fmaxf(v.z, v.w)));
        }
        float sum = 0.f;
#pragma unroll
        for (int q = 0; q < 16; q++) {
            float4 v = sp4[q];
            v.x = __expf(v.x - mx); v.y = __expf(v.y - mx);
            v.z = __expf(v.z - mx); v.w = __expf(v.w - mx);
            sum += (v.x + v.y) + (v.z + v.w);
            sp4[q] = v;
        }
        float inv = __fdividef(1.f, sum);
#pragma unroll
        for (int q = 0; q < 16; q++) {
            float4 v = sp4[q];
            unsigned long long hi, lo;
            cvt_split4(v.x * inv, v.y * inv, v.z * inv, v.w * inv, hi, lo);
            int k0 = hh * 64 + 4 * q;
            *reinterpret_cast<unsigned long long*>(Ah + r * XSTR + k0) = hi;
            *reinterpret_cast<unsigned long long*>(Al + r * XSTR + k0) = lo;
        }
    }
    CP_WAIT(0);
    __syncthreads();

    // ==================== stage 2: h = relu(alpha @ B + bo) ====================
    mma_stage(Ah, Al, Bh, Bl, m0, n0, g, tg, d);
    __syncthreads();          // stage-2 B & A reads complete

    // -------- B <- imgW (overlaps epilogue 2) --------
    cpa_img(su + SM_BH, imgW_hi, tid);
    cpa_img(su + SM_BL, imgW_lo, tid);
    CP_COMMIT();
    {
        const float* boS = reinterpret_cast<const float*>(smem + SM_BO);
#pragma unroll
        for (int nt = 0; nt < 2; nt++) {
            int c = n0 + nt * 8 + tg * 2;
            float2 bv = *reinterpret_cast<const float2*>(boS + c);
            float h00 = fmaxf(d[nt][0] + bv.x, 0.f), h01 = fmaxf(d[nt][1] + bv.y, 0.f);
            float h10 = fmaxf(d[nt][2] + bv.x, 0.f), h11 = fmaxf(d[nt][3] + bv.y, 0.f);
            *reinterpret_cast<float2*>(outH + (size_t)(row0 + m0 + g) * Dn + c)
                = make_float2(h00, h01);
            *reinterpret_cast<float2*>(outH + (size_t)(row0 + m0 + g + 8) * Dn + c)
                = make_float2(h10, h11);
            uint32_t hi, lo;
            cvt_split2(h00, h01, hi, lo);
            *reinterpret_cast<uint32_t*>(Ah + (m0 + g) * XSTR + c) = hi;
            *reinterpret_cast<uint32_t*>(Al + (m0 + g) * XSTR + c) = lo;
            cvt_split2(h10, h11, hi, lo);
            *reinterpret_cast<uint32_t*>(Ah + (m0 + g + 8) * XSTR + c) = hi;
            *reinterpret_cast<uint32_t*>(Al + (m0 + g + 8) * XSTR + c) = lo;
        }
    }
    CP_WAIT(0);
    __syncthreads();

    // ==================== stage 3: preds = h @ Wfc^T + bfc ====================
    mma_stage(Ah, Al, Bh, Bl, m0, n0, g, tg, d);
    {
        const float* bfcS = reinterpret_cast<const float*>(smem + SM_BFC);
#pragma unroll
        for (int nt = 0; nt < 2; nt++) {
            int c = n0 + nt * 8 + tg * 2;
            float2 bv = *reinterpret_cast<const float2*>(bfcS + c);
            *reinterpret_cast<float2*>(outP + (size_t)(row0 + m0 + g) * Dn + c)
                = make_float2(d[nt][0] + bv.x, d[nt][1] + bv.y);
            *reinterpret_cast<float2*>(outP + (size_t)(row0 + m0 + g + 8) * Dn + c)
                = make_float2(d[nt][2] + bv.x, d[nt][3] + bv.y);
        }
    }
}

// ============================================================
// launcher (graph-capturable: kernel launches only)
// ============================================================
extern "C" void kernel_launch(void* const* d_in, const int* in_sizes, int n_in,
                              void* d_out, int out_size) {
    const float* x       = (const float*)d_in[0];
    const float* proxies = (const float*)d_in[1];
    const float* Wq  = (const float*)d_in[2];
    const float* bq  = (const float*)d_in[3];
    const float* Wk  = (const float*)d_in[4];
    const float* bk  = (const float*)d_in[5];
    const float* Wv  = (const float*)d_in[6];
    const float* bv  = (const float*)d_in[7];
    const float* Wo  = (const float*)d_in[8];
    const float* bo  = (const float*)d_in[9];
    const float* Wfc = (const float*)d_in[10];
    const float* bfc = (const float*)d_in[11];
    // d_in[12] = edge_index : dense bipartite structure known -> unused

    float* outP = (float*)d_out;                 // preds[P:]  (S x D)
    float* outH = outP + (size_t)out_size / 2;   // h[P:]      (S x D)

    pre_all_kernel<<<Dn, NTHR>>>(proxies, Wq, bq, Wk, bk, Wv, bv, Wo, Wfc);

    cudaFuncSetAttribute(gnn_mma_kernel,
                         cudaFuncAttributeMaxDynamicSharedMemorySize, SM_TOT);
    gnn_mma_kernel<<<Sn / TM, MTHR, SM_TOT>>>(x, bo, bfc, outP, outH);
}

// round 17
// speedup vs baseline: 1.2562x; 1.2562x over previous
#include <cuda_runtime.h>
#include <cuda_bf16.h>
#include <cstdint>

#define Pn 64
#define Sn 4096
#define Dn 128
#define TM 32            // sample rows per block
#define NTHR 256
#define XSTR 136         // bf16 operand-tile k-stride (128 + 8 pad) -> conflict-free frags
#define SSTR 132         // fp32 score-tile stride

// ---------------- persistent device scratch (no allocs allowed) ----------------
__device__ __align__(16) uint16_t imgA_hi[Dn * XSTR], imgA_lo[Dn * XSTR];  // stage1 B-op
__device__ __align__(16) uint16_t imgB_hi[Dn * XSTR], imgB_lo[Dn * XSTR];  // stage2 B-op
__device__ __align__(16) uint16_t imgW_hi[Dn * XSTR], imgW_lo[Dn * XSTR];  // stage3 B-op
__device__ __align__(16) float gc[Dn];   // folded bq * K^T / 8 (stage-1 bias)

// ---------------- helpers ----------------
#define CP_COMMIT()  asm volatile("cp.async.commit_group;" ::: "memory")
#define CP_WAIT(n)   asm volatile("cp.async.wait_group %0;" :: "n"(n) : "memory")

__device__ __forceinline__ void cvt_split2(float a0, float a1, uint32_t& hi, uint32_t& lo) {
    asm("cvt.rn.bf16x2.f32 %0, %1, %2;" : "=r"(hi) : "f"(a1), "f"(a0));
    float f0 = __uint_as_float(hi << 16);
    float f1 = __uint_as_float(hi & 0xFFFF0000u);
    asm("cvt.rn.bf16x2.f32 %0, %1, %2;" : "=r"(lo) : "f"(a1 - f1), "f"(a0 - f0));
}
__device__ __forceinline__ void cvt_split4(float a0, float a1, float a2, float a3,
                                           unsigned long long& hi, unsigned long long& lo) {
    uint32_t u0, u1, v0, v1;
    cvt_split2(a0, a1, u0, v0);
    cvt_split2(a2, a3, u1, v1);
    asm("mov.b64 %0, {%1, %2};" : "=l"(hi) : "r"(u0), "r"(u1));
    asm("mov.b64 %0, {%1, %2};" : "=l"(lo) : "r"(v0), "r"(v1));
}
__device__ __forceinline__ uint32_t smem_to_u32(const void* p) {
    uint32_t a;
    asm("{ .reg .u64 t; cvta.to.shared.u64 t, %1; cvt.u32.u64 %0, t; }" : "=r"(a) : "l"(p));
    return a;
}

// ============================================================
// Single precompute kernel (unchanged from passing R15).
// ============================================================
__global__ __launch_bounds__(NTHR) void pre_all_kernel(
    const float* __restrict__ proxies,
    const float* __restrict__ Wq, const float* __restrict__ bq,
    const float* __restrict__ Wk, const float* __restrict__ bk,
    const float* __restrict__ Wv, const float* __restrict__ bv,
    const float* __restrict__ Wo, const float* __restrict__ Wfc)
{
    __shared__ __align__(16) float prS[Dn];
    __shared__ __align__(16) float kh[64];
    __shared__ __align__(16) float vh[64];

    const int col = blockIdx.x;
    const int h = col >> 6, p = col & 63;
    const int t = threadIdx.x;
    const int w = t >> 5, l = t & 31;

    if (t < 32)
        *reinterpret_cast<float4*>(prS + t * 4) =
            reinterpret_cast<const float4*>(proxies + p * Dn)[t];
    __syncthreads();

    {   // warp-cooperative dots: warps 0-3 -> kh, warps 4-7 -> vh
        const float* Wsrc = (w < 4) ? Wk : Wv;
        const float* bsrc = (w < 4) ? bk : bv;
        float* dst = (w < 4) ? kh : vh;
        const int j0 = (w & 3) * 16;
        float4 pv = *reinterpret_cast<const float4*>(prS + l * 4);
#pragma unroll
        for (int jj = 0; jj < 16; jj++) {
            int j = j0 + jj;
            float4 w4 = *reinterpret_cast<const float4*>(Wsrc + (h * 64 + j) * Dn + l * 4);
            float s = w4.x * pv.x + w4.y * pv.y + w4.z * pv.z + w4.w * pv.w;
#pragma unroll
            for (int o = 16; o; o >>= 1) s += __shfl_xor_sync(0xffffffffu, s, o);
            if (l == 0) dst[j] = s + bsrc[h * 64 + j];
        }
    }
    __syncthreads();

    if (w == 0) {   // gc[col]
        float s = bq[h * 64 + l] * kh[l] + bq[h * 64 + 32 + l] * kh[32 + l];
#pragma unroll
        for (int o = 16; o; o >>= 1) s += __shfl_xor_sync(0xffffffffu, s, o);
        if (l == 0) gc[col] = s * 0.125f;
    }

    if (t < Dn) {
        float a = 0.f;
#pragma unroll 16
        for (int j = 0; j < 64; j++) a += Wq[(h * 64 + j) * Dn + t] * kh[j];
        a *= 0.125f;
        {
            __nv_bfloat16 hb = __float2bfloat16(a);
            float fh = __bfloat162float(hb);
            __nv_bfloat16 lb = __float2bfloat16(a - fh);
            imgA_hi[col * XSTR + t] = __bfloat16_as_ushort(hb);
            imgA_lo[col * XSTR + t] = __bfloat16_as_ushort(lb);
        }
        float wv = Wfc[col * Dn + t];
        {
            __nv_bfloat16 hb = __float2bfloat16(wv);
            float fh = __bfloat162float(hb);
            __nv_bfloat16 lb = __float2bfloat16(wv - fh);
            imgW_hi[col * XSTR + t] = __bfloat16_as_ushort(hb);
            imgW_lo[col * XSTR + t] = __bfloat16_as_ushort(lb);
        }
        if (t < 8) {   // zero k-pad (determinism)
            imgA_hi[col * XSTR + Dn + t] = 0; imgA_lo[col * XSTR + Dn + t] = 0;
            imgB_hi[col * XSTR + Dn + t] = 0; imgB_lo[col * XSTR + Dn + t] = 0;
            imgW_hi[col * XSTR + Dn + t] = 0; imgW_lo[col * XSTR + Dn + t] = 0;
        }
    } else {
        const int j2 = t - Dn;
        const float4* wo = reinterpret_cast<const float4*>(Wo + j2 * Dn + h * 64);
        float s = 0.f;
#pragma unroll
        for (int q = 0; q < 16; q++) {
            float4 w4 = wo[q];
            float4 v4 = *reinterpret_cast<const float4*>(vh + q * 4);
            s += w4.x * v4.x + w4.y * v4.y + w4.z * v4.z + w4.w * v4.w;
        }
        __nv_bfloat16 hb = __float2bfloat16(s);
        float fh = __bfloat162float(hb);
        __nv_bfloat16 lb = __float2bfloat16(s - fh);
        imgB_hi[j2 * XSTR + col] = __bfloat16_as_ushort(hb);
        imgB_lo[j2 * XSTR + col] = __bfloat16_as_ushort(lb);
    }
}

// ============================================================
// Main kernel smem layout (bytes) — R15 double-slot layout
// ============================================================
#define SM_GC   0
#define SM_BO   512
#define SM_BFC  1024
#define SM_AHI  1536                         // 32*136*2 = 8704
#define SM_ALO  (SM_AHI + TM * XSTR * 2)     // 10240
#define SM_SC   (SM_ALO + TM * XSTR * 2)     // 18944 ; 32*132*4 = 16896
#define SM_B0H  (SM_SC + TM * SSTR * 4)      // 35840 ; 128*136*2 = 34816
#define SM_B0L  (SM_B0H + Dn * XSTR * 2)
#define SM_B1H  (SM_B0L + Dn * XSTR * 2)
#define SM_B1L  (SM_B1H + Dn * XSTR * 2)
#define SM_TOT  (SM_B1L + Dn * XSTR * 2)     // 175104 B

__device__ __forceinline__ void cpa_tile(uint32_t sdst, const uint16_t* src, int tid) {
#pragma unroll
    for (int i = 0; i < 9; i++) {
        int idx = tid + i * NTHR;
        if (idx < (Dn * XSTR * 2) / 16)
            asm volatile("cp.async.cg.shared.global [%0], [%1], 16;"
                         :: "r"(sdst + idx * 16), "l"((const char*)src + idx * 16));
    }
}
__device__ __forceinline__ void cp16(uint32_t d, const void* s) {
    asm volatile("cp.async.ca.shared.global [%0], [%1], 16;" :: "r"(d), "l"(s));
}

#define LDSM4(r0, r1, r2, r3, addr)                                            \
    asm volatile("ldmatrix.sync.aligned.m8n8.x4.shared.b16 {%0,%1,%2,%3}, [%4];" \
        : "=r"(r0), "=r"(r1), "=r"(r2), "=r"(r3) : "r"(addr))

#define MMA(dd, a0, a1, a2, a3, b0, b1)                                        \
    asm volatile("mma.sync.aligned.m16n8k16.row.col.f32.bf16.bf16.f32 "        \
        "{%0,%1,%2,%3}, {%4,%5,%6,%7}, {%8,%9}, {%0,%1,%2,%3};"                \
        : "+f"((dd)[0]), "+f"((dd)[1]), "+f"((dd)[2]), "+f"((dd)[3])           \
        : "r"(a0), "r"(a1), "r"(a2), "r"(a3), "r"(b0), "r"(b1))

// 3-pass split MMA via ldmatrix, pass-fused with 12 independent accumulator
// chains: d = Ahi*Bhi, e = Ahi*Blo, f = Alo*Bhi; out = d + e + f.
// aHi/aLo/bH0/bH1/bL0/bL1 are per-lane LDSM base addresses (kk-invariant).
__device__ __forceinline__ void mma_stage(
    uint32_t aHi, uint32_t aLo,
    uint32_t bH0, uint32_t bH1, uint32_t bL0, uint32_t bL1,
    float out[4][4])
{
    float d[4][4], e[4][4], f[4][4];
#pragma unroll
    for (int nt = 0; nt < 4; nt++)
#pragma unroll
        for (int i = 0; i < 4; i++) { d[nt][i] = 0.f; e[nt][i] = 0.f; f[nt][i] = 0.f; }

#pragma unroll
    for (int kk = 0; kk < 8; kk++) {
        uint32_t ah[4], al[4], bh[8], bl[8];
        LDSM4(ah[0], ah[1], ah[2], ah[3], aHi + kk * 32);
        LDSM4(al[0], al[1], al[2], al[3], aLo + kk * 32);
        LDSM4(bh[0], bh[1], bh[2], bh[3], bH0 + kk * 32);
        LDSM4(bh[4], bh[5], bh[6], bh[7], bH1 + kk * 32);
        LDSM4(bl[0], bl[1], bl[2], bl[3], bL0 + kk * 32);
        LDSM4(bl[4], bl[5], bl[6], bl[7], bL1 + kk * 32);
#pragma unroll
        for (int nt = 0; nt < 4; nt++) {
            MMA(d[nt], ah[0], ah[1], ah[2], ah[3], bh[2*nt], bh[2*nt+1]);
            MMA(e[nt], ah[0], ah[1], ah[2], ah[3], bl[2*nt], bl[2*nt+1]);
            MMA(f[nt], al[0], al[1], al[2], al[3], bh[2*nt], bh[2*nt+1]);
        }
    }
#pragma unroll
    for (int nt = 0; nt < 4; nt++)
#pragma unroll
        for (int i = 0; i < 4; i++) out[nt][i] = d[nt][i] + (e[nt][i] + f[nt][i]);
}

// ============================================================
// Main fused kernel: grid 128 (TM=32 rows), 256 threads (R15 geometry).
// Warp w: m0 = (w>>2)*16 rows, n0 = (w&3)*32 cols.
// ============================================================
__global__ __launch_bounds__(NTHR) void gnn_mma_kernel(
    const float* __restrict__ x,
    const float* __restrict__ bo, const float* __restrict__ bfc,
    float* __restrict__ outP, float* __restrict__ outH)
{
    extern __shared__ char smem[];
    const uint32_t su = smem_to_u32(smem);
    uint16_t* Ah = reinterpret_cast<uint16_t*>(smem + SM_AHI);
    uint16_t* Al = reinterpret_cast<uint16_t*>(smem + SM_ALO);
    float*    sc = reinterpret_cast<float*>(smem + SM_SC);

    const int tid = threadIdx.x;
    const int w = tid >> 5, lane = tid & 31;
    const int g = lane >> 2, tg = lane & 3;
    const int m0 = (w >> 2) * 16, n0 = (w & 3) * 32;
    const int row0 = blockIdx.x * TM;

    // per-lane ldmatrix base offsets (bytes), kk-invariant
    const int quad = lane >> 3, r8 = lane & 7;
    const uint32_t aoffB = (uint32_t)(((m0 + (quad & 1) * 8 + r8) * XSTR + (quad >> 1) * 8) << 1);
    const uint32_t boffB0 = (uint32_t)(((n0 + (quad >> 1) * 8 + r8) * XSTR + (quad & 1) * 8) << 1);
    const uint32_t boffB1 = (uint32_t)(((n0 + 16 + (quad >> 1) * 8 + r8) * XSTR + (quad & 1) * 8) << 1);
    const uint32_t aHiAd = su + SM_AHI + aoffB;
    const uint32_t aLoAd = su + SM_ALO + aoffB;

    // -------- group 1: biases + stage-1 B operand (imgA) --------
    cpa_tile(su + SM_B0H, imgA_hi, tid);
    cpa_tile(su + SM_B0L, imgA_lo, tid);
    if (tid < 32)      cp16(su + SM_GC  + tid * 16,        (const char*)gc  + tid * 16);
    else if (tid < 64) cp16(su + SM_BO  + (tid - 32) * 16, (const char*)bo  + (tid - 32) * 16);
    else if (tid < 96) cp16(su + SM_BFC + (tid - 64) * 16, (const char*)bfc + (tid - 64) * 16);
    CP_COMMIT();
    // -------- group 2: stage-2 B operand (imgB) --------
    cpa_tile(su + SM_B1H, imgB_hi, tid);
    cpa_tile(su + SM_B1L, imgB_lo, tid);
    CP_COMMIT();

    // -------- stage x -> A tiles (split bf16, padded k-major) --------
    {
        const float4* xg = reinterpret_cast<const float4*>(x + (size_t)row0 * Dn);
#pragma unroll
        for (int i = 0; i < 4; i++) {
            int idx = tid + i * NTHR;          // 0..1023 quad of 32x128 tile
            int r = idx >> 5, k0 = (idx & 31) * 4;
            float4 v = xg[idx];
            unsigned long long hi, lo;
            cvt_split4(v.x, v.y, v.z, v.w, hi, lo);
            *reinterpret_cast<unsigned long long*>(Ah + r * XSTR + k0) = hi;
            *reinterpret_cast<unsigned long long*>(Al + r * XSTR + k0) = lo;
        }
    }
    CP_WAIT(1);               // group 1 done (biases + B0); group 2 may be in flight
    __syncthreads();

    float d[4][4];

    // ==================== stage 1: scores = x @ A + gc ====================
    mma_stage(aHiAd, aLoAd,
              su + SM_B0H + boffB0, su + SM_B0H + boffB1,
              su + SM_B0L + boffB0, su + SM_B0L + boffB1, d);
    {
        const float* gcS = reinterpret_cast<const float*>(smem + SM_GC);
#pragma unroll
        for (int nt = 0; nt < 4; nt++) {
            int c = n0 + nt * 8 + tg * 2;
            float2 bv = *reinterpret_cast<const float2*>(gcS + c);
            *reinterpret_cast<float2*>(sc + (m0 + g) * SSTR + c)
                = make_float2(d[nt][0] + bv.x, d[nt][1] + bv.y);
            *reinterpret_cast<float2*>(sc + (m0 + g + 8) * SSTR + c)
                = make_float2(d[nt][2] + bv.x, d[nt][3] + bv.y);
        }
    }
    __syncthreads();          // all stage-1 work done: B0 & A free for rewrite

    // -------- group 3: stage-3 B operand (imgW) -> B0 ; softmax -> alpha in A ----
    cpa_tile(su + SM_B0H, imgW_hi, tid);
    cpa_tile(su + SM_B0L, imgW_lo, tid);
    CP_COMMIT();
    if (tid < 64) {           // one (row, head) per thread: softmax over 64 proxies
        const int r = tid >> 1, hh = tid & 1;
        float4* sp4 = reinterpret_cast<float4*>(sc + r * SSTR + hh * 64);
        float mx = -1e30f;
#pragma unroll
        for (int q = 0; q < 16; q++) {
            float4 v = sp4[q];
            mx = fmaxf(mx, fmaxf(fmaxf(v.x, v.y), fmaxf(v.z, v.w)));
        }
        float sum = 0.f;
        float vv[64];
#pragma unroll
        for (int q = 0; q < 16; q++) {
            float4 v = sp4[q];
            vv[4*q+0] = __expf(v.x - mx); vv[4*q+1] = __expf(v.y - mx);
            vv[4*q+2] = __expf(v.z - mx); vv[4*q+3] = __expf(v.w - mx);
            sum += (vv[4*q] + vv[4*q+1]) + (vv[4*q+2] + vv[4*q+3]);
        }
        float inv = __fdividef(1.f, sum);
#pragma unroll
        for (int q = 0; q < 16; q++) {
            unsigned long long hi, lo;
            cvt_split4(vv[4*q]*inv, vv[4*q+1]*inv, vv[4*q+2]*inv, vv[4*q+3]*inv, hi, lo);
            int k0 = hh * 64 + 4 * q;
            *reinterpret_cast<unsigned long long*>(Ah + r * XSTR + k0) = hi;
            *reinterpret_cast<unsigned long long*>(Al + r * XSTR + k0) = lo;
        }
    }
    CP_WAIT(1);               // group 2 (B1 = imgB) done; group 3 may be in flight
    __syncthreads();

    // ==================== stage 2: h = relu(alpha @ B + bo) ====================
    mma_stage(aHiAd, aLoAd,
              su + SM_B1H + boffB0, su + SM_B1H + boffB1,
              su + SM_B1L + boffB0, su + SM_B1L + boffB1, d);
    __syncthreads();          // all stage-2 A reads done before overwrite
    {
        const float* boS = reinterpret_cast<const float*>(smem + SM_BO);
#pragma unroll
        for (int nt = 0; nt < 4; nt++) {
            int c = n0 + nt * 8 + tg * 2;
            float2 bv = *reinterpret_cast<const float2*>(boS + c);
            float h00 = fmaxf(d[nt][0] + bv.x, 0.f), h01 = fmaxf(d[nt][1] + bv.y, 0.f);
            float h10 = fmaxf(d[nt][2] + bv.x, 0.f), h11 = fmaxf(d[nt][3] + bv.y, 0.f);
            *reinterpret_cast<float2*>(outH + (size_t)(row0 + m0 + g) * Dn + c)
                = make_float2(h00, h01);
            *reinterpret_cast<float2*>(outH + (size_t)(row0 + m0 + g + 8) * Dn + c)
                = make_float2(h10, h11);
            uint32_t hi, lo;
            cvt_split2(h00, h01, hi, lo);
            *reinterpret_cast<uint32_t*>(Ah + (m0 + g) * XSTR + c) = hi;
            *reinterpret_cast<uint32_t*>(Al + (m0 + g) * XSTR + c) = lo;
            cvt_split2(h10, h11, hi, lo);
            *reinterpret_cast<uint32_t*>(Ah + (m0 + g + 8) * XSTR + c) = hi;
            *reinterpret_cast<uint32_t*>(Al + (m0 + g + 8) * XSTR + c) = lo;
        }
    }
    CP_WAIT(0);               // group 3 (B0 = imgW) done
    __syncthreads();

    // ==================== stage 3: preds = h @ Wfc^T + bfc ====================
    mma_stage(aHiAd, aLoAd,
              su + SM_B0H + boffB0, su + SM_B0H + boffB1,
              su + SM_B0L + boffB0, su + SM_B0L + boffB1, d);
    {
        const float* bfcS = reinterpret_cast<const float*>(smem + SM_BFC);
#pragma unroll
        for (int nt = 0; nt < 4; nt++) {
            int c = n0 + nt * 8 + tg * 2;
            float2 bv = *reinterpret_cast<const float2*>(bfcS + c);
            *reinterpret_cast<float2*>(outP + (size_t)(row0 + m0 + g) * Dn + c)
                = make_float2(d[nt][0] + bv.x, d[nt][1] + bv.y);
            *reinterpret_cast<float2*>(outP + (size_t)(row0 + m0 + g + 8) * Dn + c)
                = make_float2(d[nt][2] + bv.x, d[nt][3] + bv.y);
        }
    }
}

// ============================================================
// launcher (graph-capturable: kernel launches only)
// ============================================================
extern "C" void kernel_launch(void* const* d_in, const int* in_sizes, int n_in,
                              void* d_out, int out_size) {
    const float* x       = (const float*)d_in[0];
    const float* proxies = (const float*)d_in[1];
    const float* Wq  = (const float*)d_in[2];
    const float* bq  = (const float*)d_in[3];
    const float* Wk  = (const float*)d_in[4];
    const float* bk  = (const float*)d_in[5];
    const float* Wv  = (const float*)d_in[6];
    const float* bv  = (const float*)d_in[7];
    const float* Wo  = (const float*)d_in[8];
    const float* bo  = (const float*)d_in[9];
    const float* Wfc = (const float*)d_in[10];
    const float* bfc = (const float*)d_in[11];
    // d_in[12] = edge_index : dense bipartite structure known -> unused

    float* outP = (float*)d_out;                 // preds[P:]  (S x D)
    float* outH = outP + (size_t)out_size / 2;   // h[P:]      (S x D)

    pre_all_kernel<<<Dn, NTHR>>>(proxies, Wq, bq, Wk, bk, Wv, bv, Wo, Wfc);

    cudaFuncSetAttribute(gnn_mma_kernel,
                         cudaFuncAttributeMaxDynamicSharedMemorySize, SM_TOT);
    gnn_mma_kernel<<<Sn / TM, NTHR, SM_TOT>>>(x, bo, bfc, outP, outH);
}